// round 14
// baseline (speedup 1.0000x reference)
#include <cuda_runtime.h>
#include <cuda_fp16.h>

#define N_NODES 50000
#define N_EDGES 800000
#define ET (N_EDGES + N_NODES)   // edges + self loops
#define EQ4 (N_EDGES/4)          // 200000
#define F_IN 128
#define HEADS 4
#define HID 64
#define HH (HEADS*HID)           // 256
#define NEG 0.2f

#define SCAN_BLK 512
#define NB ((N_NODES + SCAN_BLK - 1) / SCAN_BLK)   // 98

// -------- device scratch (static: no allocation allowed) --------
__device__ __align__(16) __half    g_w1h[F_IN*HH];        // W1 in fp16
__device__ __align__(16) __half2   g_h1h[N_NODES*128];    // layer1 features (fp16)
__device__ __align__(16) float     g_as1[N_NODES*HEADS];
__device__ __align__(16) float     g_ad1[N_NODES*HEADS];
__device__ __align__(16) int       g_deg[N_NODES];
__device__ __align__(16) int       g_cur[N_NODES];
__device__ __align__(16) int       g_scan[N_NODES];
__device__ __align__(16) int       g_off[N_NODES];
__device__ __align__(16) int       g_bsum[NB];
__device__ __align__(16) int       g_adj[ET];             // CSR: src per incoming slot
__device__ __align__(16) float     g_h2[N_NODES*2];
__device__ __align__(16) float     g_as2[N_NODES];
__device__ __align__(16) float     g_ad2[N_NODES];
__device__ int g_fmt64;

__device__ __forceinline__ float lrelu(float x) { return x > 0.f ? x : NEG * x; }

__device__ __forceinline__ unsigned s2u(const void* p) {
    return (unsigned)__cvta_generic_to_shared(p);
}
__device__ __forceinline__ void ldmat4(unsigned& r0, unsigned& r1, unsigned& r2, unsigned& r3, unsigned addr) {
    asm volatile("ldmatrix.sync.aligned.m8n8.x4.shared.b16 {%0,%1,%2,%3}, [%4];"
                 : "=r"(r0), "=r"(r1), "=r"(r2), "=r"(r3) : "r"(addr));
}
__device__ __forceinline__ void ldmat4t(unsigned& r0, unsigned& r1, unsigned& r2, unsigned& r3, unsigned addr) {
    asm volatile("ldmatrix.sync.aligned.m8n8.x4.trans.shared.b16 {%0,%1,%2,%3}, [%4];"
                 : "=r"(r0), "=r"(r1), "=r"(r2), "=r"(r3) : "r"(addr));
}
__device__ __forceinline__ void mma16816(float* c, const unsigned* a, unsigned b0, unsigned b1) {
    asm volatile("mma.sync.aligned.m16n8k16.row.col.f32.f16.f16.f32 "
                 "{%0,%1,%2,%3}, {%4,%5,%6,%7}, {%8,%9}, {%0,%1,%2,%3};"
                 : "+f"(c[0]), "+f"(c[1]), "+f"(c[2]), "+f"(c[3])
                 : "r"(a[0]), "r"(a[1]), "r"(a[2]), "r"(a[3]), "r"(b0), "r"(b1));
}

// -------- zero degree counters + detect edge dtype + convert W1 --------
#define CVT_W_CHUNKS (F_IN*HH/4)   // 8192
__global__ void k_zero(const int* __restrict__ ei32, const float* __restrict__ w) {
    int i = blockIdx.x * blockDim.x + threadIdx.x;
    if (i < N_NODES) { g_deg[i] = 1; g_cur[i] = 0; }   // deg=1 seeds self loop
    if (i < CVT_W_CHUNKS) {
        float4 v = ((const float4*)w)[i];
        __half2 a = __floats2half2_rn(v.x, v.y);
        __half2 b = __floats2half2_rn(v.z, v.w);
        uint2 st; st.x = *(unsigned*)&a; st.y = *(unsigned*)&b;
        ((uint2*)g_w1h)[i] = st;
    }
    if (blockIdx.x == 0) {
        __shared__ int nz;
        if (threadIdx.x == 0) nz = 0;
        __syncthreads();
        int c = 0;
        for (int k = threadIdx.x; k < 1024; k += blockDim.x)
            if (ei32[2*k + 1] != 0) c++;
        atomicAdd(&nz, c);
        __syncthreads();
        if (threadIdx.x == 0) g_fmt64 = (nz == 0) ? 1 : 0;
    }
}

// -------- count in-degrees (4 edges/thread, vectorized loads) --------
__global__ void k_count(const void* __restrict__ ei) {
    int t = blockIdx.x * blockDim.x + threadIdx.x;
    if (t >= EQ4) return;
    int d0, d1, d2, d3;
    if (g_fmt64) {
        const longlong2* ed = (const longlong2*)((const long long*)ei + N_EDGES);
        longlong2 a = ed[t*2], b = ed[t*2+1];
        d0 = (int)a.x; d1 = (int)a.y; d2 = (int)b.x; d3 = (int)b.y;
    } else {
        int4 v = ((const int4*)((const int*)ei + N_EDGES))[t];
        d0 = v.x; d1 = v.y; d2 = v.z; d3 = v.w;
    }
    atomicAdd(&g_deg[d0], 1);
    atomicAdd(&g_deg[d1], 1);
    atomicAdd(&g_deg[d2], 1);
    atomicAdd(&g_deg[d3], 1);
}

// -------- scan stage 1 --------
__global__ void k_scan1() {
    __shared__ int s[SCAN_BLK];
    int t = threadIdx.x;
    int i = blockIdx.x * SCAN_BLK + t;
    int v = (i < N_NODES) ? g_deg[i] : 0;
    s[t] = v;
    __syncthreads();
    for (int off = 1; off < SCAN_BLK; off <<= 1) {
        int x = (t >= off) ? s[t - off] : 0;
        __syncthreads();
        s[t] += x;
        __syncthreads();
    }
    if (i < N_NODES) g_scan[i] = s[t] - v;
    if (t == SCAN_BLK - 1) g_bsum[blockIdx.x] = s[t];
}

// -------- scan stages 2+3 merged --------
__global__ void k_scan23() {
    __shared__ int sb[NB];
    int t = threadIdx.x;
    if (t < NB) sb[t] = g_bsum[t];
    __syncthreads();
    if (t == 0) {
        int run = 0;
        for (int k = 0; k < NB; k++) { int v = sb[k]; sb[k] = run; run += v; }
    }
    __syncthreads();
    int i = blockIdx.x * blockDim.x + t;
    if (i < N_NODES) g_off[i] = g_scan[i] + sb[i / SCAN_BLK];
}

// -------- fill CSR (4 edges/thread + self-loop range) --------
__global__ void k_fill(const void* __restrict__ ei) {
    int t = blockIdx.x * blockDim.x + threadIdx.x;
    if (t < EQ4) {
        int s0,s1,s2,s3,d0,d1,d2,d3;
        if (g_fmt64) {
            const longlong2* es = (const longlong2*)ei;
            const longlong2* ed = (const longlong2*)((const long long*)ei + N_EDGES);
            longlong2 sa = es[t*2], sb = es[t*2+1];
            longlong2 da = ed[t*2], db = ed[t*2+1];
            s0=(int)sa.x; s1=(int)sa.y; s2=(int)sb.x; s3=(int)sb.y;
            d0=(int)da.x; d1=(int)da.y; d2=(int)db.x; d3=(int)db.y;
        } else {
            int4 sv = ((const int4*)ei)[t];
            int4 dv = ((const int4*)((const int*)ei + N_EDGES))[t];
            s0=sv.x; s1=sv.y; s2=sv.z; s3=sv.w;
            d0=dv.x; d1=dv.y; d2=dv.z; d3=dv.w;
        }
        int p0 = atomicAdd(&g_cur[d0], 1); g_adj[g_off[d0] + p0] = s0;
        int p1 = atomicAdd(&g_cur[d1], 1); g_adj[g_off[d1] + p1] = s1;
        int p2 = atomicAdd(&g_cur[d2], 1); g_adj[g_off[d2] + p2] = s2;
        int p3 = atomicAdd(&g_cur[d3], 1); g_adj[g_off[d3] + p3] = s3;
    } else {
        int n = t - EQ4;
        if (n < N_NODES) {
            int p = atomicAdd(&g_cur[n], 1);
            g_adj[g_off[n] + p] = n;
        }
    }
}

// -------- tensor-core GEMM: single K-stage (K=128 resident in SMEM) ----
#define PADH 136
#define MMA_SMEM (2*128*PADH*2)
__global__ void __launch_bounds__(256, 2)
k_mma(const float* __restrict__ X,
      const float* __restrict__ attS, const float* __restrict__ attD) {
    extern __shared__ __half dynsmem[];
    __half (*As)[PADH] = (__half(*)[PADH])dynsmem;
    __half (*Bs)[PADH] = (__half(*)[PADH])(dynsmem + 128*PADH);
    const int t    = threadIdx.x;
    const int lane = t & 31;
    const int wid  = t >> 5;
    const int wm   = wid & 3;
    const int wn   = wid >> 2;
    const int bm   = blockIdx.x * 128;
    const int bn   = blockIdx.y * 128;

#pragma unroll
    for (int it = 0; it < 8; it++) {
        int c  = t + it*256;
        int r  = c >> 4, cc = c & 15;
        int gr = bm + r;
        uint4 st = make_uint4(0u, 0u, 0u, 0u);
        if (gr < N_NODES) {
            const float4* xp = (const float4*)(X + (size_t)gr*F_IN + cc*8);
            float4 f0 = xp[0];
            float4 f1 = xp[1];
            __half2 h0 = __floats2half2_rn(f0.x, f0.y);
            __half2 h1 = __floats2half2_rn(f0.z, f0.w);
            __half2 h2 = __floats2half2_rn(f1.x, f1.y);
            __half2 h3 = __floats2half2_rn(f1.z, f1.w);
            st.x = *(unsigned*)&h0; st.y = *(unsigned*)&h1;
            st.z = *(unsigned*)&h2; st.w = *(unsigned*)&h3;
        }
        *(uint4*)&As[r][cc*8] = st;
    }
#pragma unroll
    for (int it = 0; it < 8; it++) {
        int c  = t + it*256;
        int kr = c >> 4, cc = c & 15;
        uint4 v = *(const uint4*)(g_w1h + (size_t)kr*HH + bn + cc*8);
        *(uint4*)&Bs[kr][cc*8] = v;
    }
    __syncthreads();

    float acc[2][8][4];
#pragma unroll
    for (int i = 0; i < 2; i++)
#pragma unroll
        for (int j = 0; j < 8; j++)
#pragma unroll
            for (int k = 0; k < 4; k++) acc[i][j][k] = 0.f;

    const int quad = lane >> 3;
#pragma unroll
    for (int ks = 0; ks < 8; ks++) {
        unsigned a[2][4];
#pragma unroll
        for (int mi = 0; mi < 2; mi++) {
            int row = wm*32 + mi*16 + (lane & 7) + (quad & 1)*8;
            int col = ks*16 + (quad >> 1)*8;
            ldmat4(a[mi][0], a[mi][1], a[mi][2], a[mi][3], s2u(&As[row][col]));
        }
        unsigned b[4][4];
#pragma unroll
        for (int ni = 0; ni < 4; ni++) {
            int krow = ks*16 + (lane & 7) + (quad & 1)*8;
            int col  = wn*64 + ni*16 + (quad >> 1)*8;
            ldmat4t(b[ni][0], b[ni][1], b[ni][2], b[ni][3], s2u(&Bs[krow][col]));
        }
#pragma unroll
        for (int mi = 0; mi < 2; mi++)
#pragma unroll
            for (int ni = 0; ni < 4; ni++) {
                mma16816(acc[mi][ni*2],   a[mi], b[ni][0], b[ni][1]);
                mma16816(acc[mi][ni*2+1], a[mi], b[ni][2], b[ni][3]);
            }
    }

    const int head = (bn >> 6) + wn;
#pragma unroll
    for (int mi = 0; mi < 2; mi++) {
        int r0 = bm + wm*32 + mi*16 + (lane >> 2);
        float pS0 = 0.f, pD0 = 0.f, pS8 = 0.f, pD8 = 0.f;
#pragma unroll
        for (int nj = 0; nj < 8; nj++) {
            int col = bn + wn*64 + nj*8 + (lane & 3)*2;
            float c0 = acc[mi][nj][0], c1 = acc[mi][nj][1];
            float c2 = acc[mi][nj][2], c3 = acc[mi][nj][3];
            float sS0 = attS[col], sS1 = attS[col+1];
            float sD0 = attD[col], sD1 = attD[col+1];
            pS0 += c0*sS0 + c1*sS1;  pD0 += c0*sD0 + c1*sD1;
            pS8 += c2*sS0 + c3*sS1;  pD8 += c2*sD0 + c3*sD1;
            if (r0 < N_NODES)
                g_h1h[(size_t)r0*128 + (col >> 1)] = __floats2half2_rn(c0, c1);
            if (r0 + 8 < N_NODES)
                g_h1h[(size_t)(r0+8)*128 + (col >> 1)] = __floats2half2_rn(c2, c3);
        }
#pragma unroll
        for (int o = 1; o <= 2; o <<= 1) {
            pS0 += __shfl_xor_sync(0xffffffffu, pS0, o);
            pD0 += __shfl_xor_sync(0xffffffffu, pD0, o);
            pS8 += __shfl_xor_sync(0xffffffffu, pS8, o);
            pD8 += __shfl_xor_sync(0xffffffffu, pD8, o);
        }
        if ((lane & 3) == 0) {
            if (r0 < N_NODES)     { g_as1[r0*4 + head]     = pS0; g_ad1[r0*4 + head]     = pD0; }
            if (r0 + 8 < N_NODES) { g_as1[(r0+8)*4 + head] = pS8; g_ad1[(r0+8)*4 + head] = pD8; }
        }
    }
}

// accumulate 8 fp16 channels of one src row, weighted
__device__ __forceinline__ void agg8(float4 hv, float eh, float* acc) {
    const __half2* ph = (const __half2*)&hv;
    float2 q0 = __half22float2(ph[0]);
    float2 q1 = __half22float2(ph[1]);
    float2 q2 = __half22float2(ph[2]);
    float2 q3 = __half22float2(ph[3]);
    acc[0] += eh*q0.x; acc[1] += eh*q0.y;
    acc[2] += eh*q1.x; acc[3] += eh*q1.y;
    acc[4] += eh*q2.x; acc[5] += eh*q2.y;
    acc[6] += eh*q3.x; acc[7] += eh*q3.y;
}

// -------- fused layer1: 2 warps per dst, EDGE-split (no duplicated work) ----
// Warp pair (2q, 2q+1) handles dst = blockIdx*4 + q. Each warp takes alternating
// 32-edge batches; every edge is staged/exp'd/gathered by exactly one warp.
// Partials (acc[256] + z[4]) combined via smem; even warp runs the epilogue.
__global__ void __launch_bounds__(256)
k_fused1(const float* __restrict__ b1, const float* __restrict__ W2,
         const float* __restrict__ attS2, const float* __restrict__ attD2) {
    __shared__ __align__(16) int   sid[8][32];
    __shared__ __align__(16) float sex[8][4][32];
    __shared__ __align__(16) float spacc[4][256];
    __shared__ float spz[4][4];
    const int warp = threadIdx.x >> 5;
    const int lane = threadIdx.x & 31;
    const int q    = warp >> 1;                    // pair index 0..3
    const int half = warp & 1;                     // which half of edge batches
    const int w    = blockIdx.x * 4 + q;           // N_NODES % 4 == 0
    const int beg  = g_off[w];
    const int end  = beg + g_deg[w];
    float4 ad = *(const float4*)(g_ad1 + w*4);

    const int hd = lane >> 3;            // head of this lane's channels [lane*8 .. +7]
    float acc[8] = {0.f,0.f,0.f,0.f,0.f,0.f,0.f,0.f};
    float4 zs = make_float4(0.f, 0.f, 0.f, 0.f);
    const float4* hp = (const float4*)g_h1h;

    for (int base = beg + half*32; base < end; base += 64) {
        int j = base + lane;
        int s = 0;
        float4 ex = make_float4(0.f, 0.f, 0.f, 0.f);
        if (j < end) {
            s = g_adj[j];
            float4 as = *(const float4*)(g_as1 + s*4);
            ex.x = __expf(lrelu(as.x + ad.x));
            ex.y = __expf(lrelu(as.y + ad.y));
            ex.z = __expf(lrelu(as.z + ad.z));
            ex.w = __expf(lrelu(as.w + ad.w));
            zs.x += ex.x; zs.y += ex.y; zs.z += ex.z; zs.w += ex.w;
        }
        sid[warp][lane]    = s;
        sex[warp][0][lane] = ex.x;
        sex[warp][1][lane] = ex.y;
        sex[warp][2][lane] = ex.z;
        sex[warp][3][lane] = ex.w;
        __syncwarp();
        int cnt = min(32, end - base);
        int jj = 0;
        for (; jj + 8 <= cnt; jj += 8) {
            int4 ia = *(const int4*)&sid[warp][jj];
            int4 ib = *(const int4*)&sid[warp][jj+4];
            float4 wa = *(const float4*)&sex[warp][hd][jj];
            float4 wb = *(const float4*)&sex[warp][hd][jj+4];
            float4 v0 = hp[(size_t)ia.x*32 + lane];
            float4 v1 = hp[(size_t)ia.y*32 + lane];
            float4 v2 = hp[(size_t)ia.z*32 + lane];
            float4 v3 = hp[(size_t)ia.w*32 + lane];
            float4 v4 = hp[(size_t)ib.x*32 + lane];
            float4 v5 = hp[(size_t)ib.y*32 + lane];
            float4 v6 = hp[(size_t)ib.z*32 + lane];
            float4 v7 = hp[(size_t)ib.w*32 + lane];
            agg8(v0, wa.x, acc); agg8(v1, wa.y, acc);
            agg8(v2, wa.z, acc); agg8(v3, wa.w, acc);
            agg8(v4, wb.x, acc); agg8(v5, wb.y, acc);
            agg8(v6, wb.z, acc); agg8(v7, wb.w, acc);
        }
        for (; jj < cnt; jj++) {
            int   ss = sid[warp][jj];
            float eh = sex[warp][hd][jj];
            float4 v = hp[(size_t)ss*32 + lane];
            agg8(v, eh, acc);
        }
        __syncwarp();
    }
#pragma unroll
    for (int o = 16; o >= 1; o >>= 1) {
        zs.x += __shfl_xor_sync(0xffffffffu, zs.x, o);
        zs.y += __shfl_xor_sync(0xffffffffu, zs.y, o);
        zs.z += __shfl_xor_sync(0xffffffffu, zs.z, o);
        zs.w += __shfl_xor_sync(0xffffffffu, zs.w, o);
    }
    // odd warp publishes its partials; even warp combines + epilogue
    if (half) {
        *(float4*)&spacc[q][lane*8]     = make_float4(acc[0], acc[1], acc[2], acc[3]);
        *(float4*)&spacc[q][lane*8 + 4] = make_float4(acc[4], acc[5], acc[6], acc[7]);
        if (lane == 0) *(float4*)&spz[q][0] = zs;
    }
    __syncthreads();
    if (half) return;

    float4 pz = *(const float4*)&spz[q][0];
    zs.x += pz.x; zs.y += pz.y; zs.z += pz.z; zs.w += pz.w;
    float4 pa = *(const float4*)&spacc[q][lane*8];
    float4 pb = *(const float4*)&spacc[q][lane*8 + 4];
    acc[0] += pa.x; acc[1] += pa.y; acc[2] += pa.z; acc[3] += pa.w;
    acc[4] += pb.x; acc[5] += pb.y; acc[6] += pb.z; acc[7] += pb.w;

    float zh = (hd == 0) ? zs.x : (hd == 1) ? zs.y : (hd == 2) ? zs.z : zs.w;
    float4 bA = *(const float4*)(b1 + lane*8);
    float4 bB = *(const float4*)(b1 + lane*8 + 4);
    float o0 = acc[0]/zh + bA.x, o1 = acc[1]/zh + bA.y;
    float o2 = acc[2]/zh + bA.z, o3 = acc[3]/zh + bA.w;
    float o4 = acc[4]/zh + bB.x, o5 = acc[5]/zh + bB.y;
    float o6 = acc[6]/zh + bB.z, o7 = acc[7]/zh + bB.w;
    o0 = o0 > 0.f ? o0 : (__expf(o0) - 1.f);
    o1 = o1 > 0.f ? o1 : (__expf(o1) - 1.f);
    o2 = o2 > 0.f ? o2 : (__expf(o2) - 1.f);
    o3 = o3 > 0.f ? o3 : (__expf(o3) - 1.f);
    o4 = o4 > 0.f ? o4 : (__expf(o4) - 1.f);
    o5 = o5 > 0.f ? o5 : (__expf(o5) - 1.f);
    o6 = o6 > 0.f ? o6 : (__expf(o6) - 1.f);
    o7 = o7 > 0.f ? o7 : (__expf(o7) - 1.f);
    const float4* Wv = (const float4*)(W2 + lane*16);
    float4 w0 = Wv[0], w1 = Wv[1], w2 = Wv[2], w3 = Wv[3];
    float s0 = o0*w0.x + o1*w0.z + o2*w1.x + o3*w1.z
             + o4*w2.x + o5*w2.z + o6*w3.x + o7*w3.z;
    float s1 = o0*w0.y + o1*w0.w + o2*w1.y + o3*w1.w
             + o4*w2.y + o5*w2.w + o6*w3.y + o7*w3.w;
#pragma unroll
    for (int o = 16; o >= 1; o >>= 1) {
        s0 += __shfl_xor_sync(0xffffffffu, s0, o);
        s1 += __shfl_xor_sync(0xffffffffu, s1, o);
    }
    if (lane == 0) {
        g_h2[w*2]   = s0;
        g_h2[w*2+1] = s1;
        g_as2[w] = s0*attS2[0] + s1*attS2[1];
        g_ad2[w] = s0*attD2[0] + s1*attD2[1];
    }
}

// -------- fused layer2 (thread per dst, 4-deep MLP unroll) --------
__global__ void k_fused2(float* __restrict__ out, const float* __restrict__ b2) {
    int t = blockIdx.x * blockDim.x + threadIdx.x;
    if (t >= N_NODES) return;
    const int beg = g_off[t];
    const int end = beg + g_deg[t];
    const float ad = g_ad2[t];
    float z = 0.f, a0 = 0.f, a1 = 0.f;
    int j = beg;
    for (; j + 4 <= end; j += 4) {
        int s0 = g_adj[j], s1 = g_adj[j+1], s2 = g_adj[j+2], s3 = g_adj[j+3];
        float q0 = g_as2[s0], q1 = g_as2[s1], q2 = g_as2[s2], q3 = g_as2[s3];
        float2 h0 = *(const float2*)(g_h2 + 2*s0);
        float2 h1 = *(const float2*)(g_h2 + 2*s1);
        float2 h2 = *(const float2*)(g_h2 + 2*s2);
        float2 h3 = *(const float2*)(g_h2 + 2*s3);
        float e0 = __expf(lrelu(q0 + ad));
        float e1 = __expf(lrelu(q1 + ad));
        float e2 = __expf(lrelu(q2 + ad));
        float e3 = __expf(lrelu(q3 + ad));
        z  += e0 + e1 + e2 + e3;
        a0 += e0*h0.x + e1*h1.x + e2*h2.x + e3*h3.x;
        a1 += e0*h0.y + e1*h1.y + e2*h2.y + e3*h3.y;
    }
    for (; j < end; j++) {
        int s = g_adj[j];
        float ex = __expf(lrelu(g_as2[s] + ad));
        float2 h = *(const float2*)(g_h2 + 2*s);
        z  += ex;
        a0 += ex * h.x;
        a1 += ex * h.y;
    }
    out[2*t]   = a0 / z + b2[0];
    out[2*t+1] = a1 / z + b2[1];
}

extern "C" void kernel_launch(void* const* d_in, const int* in_sizes, int n_in,
                              void* d_out, int out_size) {
    const float* x    = (const float*)d_in[0];
    const void*  ei   = d_in[1];
    const float* W1   = (const float*)d_in[2];
    const float* aS1  = (const float*)d_in[3];
    const float* aD1  = (const float*)d_in[4];
    const float* b1   = (const float*)d_in[5];
    const float* W2   = (const float*)d_in[6];
    const float* aS2  = (const float*)d_in[7];
    const float* aD2  = (const float*)d_in[8];
    const float* b2   = (const float*)d_in[9];
    float* out = (float*)d_out;

    cudaFuncSetAttribute(k_mma, cudaFuncAttributeMaxDynamicSharedMemorySize, MMA_SMEM);

    cudaStream_t s1 = 0;
    cudaEvent_t evA = 0, evB = 0;
    bool par = (cudaStreamCreateWithFlags(&s1, cudaStreamNonBlocking) == cudaSuccess);
    if (par) par = (cudaEventCreateWithFlags(&evA, cudaEventDisableTiming) == cudaSuccess);
    if (par) par = (cudaEventCreateWithFlags(&evB, cudaEventDisableTiming) == cudaSuccess);
    cudaStream_t sb = par ? s1 : 0;

    const int TB = 256;
    k_zero<<<(N_NODES + TB - 1) / TB, TB>>>((const int*)ei, W1);
    if (par) {
        cudaEventRecord(evA, 0);
        cudaStreamWaitEvent(s1, evA, 0);
    }
    dim3 gg((N_NODES + 127) / 128, HH / 128);
    k_mma<<<gg, 256, MMA_SMEM>>>(x, aS1, aD1);
    k_count<<<(EQ4 + TB - 1) / TB, TB, 0, sb>>>(ei);
    k_scan1<<<NB, SCAN_BLK, 0, sb>>>();
    k_scan23<<<(N_NODES + TB - 1) / TB, TB, 0, sb>>>();
    k_fill<<<(EQ4 + N_NODES + TB - 1) / TB, TB, 0, sb>>>(ei);
    if (par) {
        cudaEventRecord(evB, s1);
        cudaStreamWaitEvent(0, evB, 0);
    }
    k_fused1<<<N_NODES / 4, TB>>>(b1, W2, aS2, aD2);
    k_fused2<<<(N_NODES + TB - 1) / TB, TB>>>(out, b2);
}

// round 15
// speedup vs baseline: 1.3731x; 1.3731x over previous
#include <cuda_runtime.h>
#include <cuda_fp16.h>

#define N_NODES 50000
#define N_EDGES 800000
#define ET (N_EDGES + N_NODES)   // edges + self loops
#define EQ4 (N_EDGES/4)          // 200000
#define F_IN 128
#define HEADS 4
#define HID 64
#define HH (HEADS*HID)           // 256
#define NEG 0.2f

#define SCAN_BLK 512
#define NB ((N_NODES + SCAN_BLK - 1) / SCAN_BLK)   // 98

// -------- device scratch (static: no allocation allowed) --------
__device__ __align__(16) __half    g_w1h[F_IN*HH];        // W1 in fp16
__device__ __align__(16) __half2   g_h1h[N_NODES*128];    // layer1 features (fp16)
__device__ __align__(16) float     g_as1[N_NODES*HEADS];
__device__ __align__(16) float     g_ad1[N_NODES*HEADS];
__device__ __align__(16) int       g_deg[N_NODES];
__device__ __align__(16) int       g_cur[N_NODES];
__device__ __align__(16) int       g_scan[N_NODES];
__device__ __align__(16) int       g_off[N_NODES];
__device__ __align__(16) int       g_bsum[NB];
__device__ __align__(16) int       g_adj[ET];             // CSR: src per incoming slot
__device__ __align__(16) float4    g_n2[N_NODES];         // (h2.x, h2.y, as2, unused)
__device__ __align__(16) float     g_ad2[N_NODES];
__device__ int g_fmt64;

__device__ __forceinline__ float lrelu(float x) { return x > 0.f ? x : NEG * x; }

__device__ __forceinline__ unsigned s2u(const void* p) {
    return (unsigned)__cvta_generic_to_shared(p);
}
__device__ __forceinline__ void ldmat4(unsigned& r0, unsigned& r1, unsigned& r2, unsigned& r3, unsigned addr) {
    asm volatile("ldmatrix.sync.aligned.m8n8.x4.shared.b16 {%0,%1,%2,%3}, [%4];"
                 : "=r"(r0), "=r"(r1), "=r"(r2), "=r"(r3) : "r"(addr));
}
__device__ __forceinline__ void ldmat4t(unsigned& r0, unsigned& r1, unsigned& r2, unsigned& r3, unsigned addr) {
    asm volatile("ldmatrix.sync.aligned.m8n8.x4.trans.shared.b16 {%0,%1,%2,%3}, [%4];"
                 : "=r"(r0), "=r"(r1), "=r"(r2), "=r"(r3) : "r"(addr));
}
__device__ __forceinline__ void mma16816(float* c, const unsigned* a, unsigned b0, unsigned b1) {
    asm volatile("mma.sync.aligned.m16n8k16.row.col.f32.f16.f16.f32 "
                 "{%0,%1,%2,%3}, {%4,%5,%6,%7}, {%8,%9}, {%0,%1,%2,%3};"
                 : "+f"(c[0]), "+f"(c[1]), "+f"(c[2]), "+f"(c[3])
                 : "r"(a[0]), "r"(a[1]), "r"(a[2]), "r"(a[3]), "r"(b0), "r"(b1));
}

#define PACK2(d, lo, hi) asm("mov.b64 %0, {%1, %2};" : "=l"(d) : "f"(lo), "f"(hi))
#define UNPACK2(lo, hi, s) asm("mov.b64 {%0, %1}, %2;" : "=f"(lo), "=f"(hi) : "l"(s))
#define FMA2(acc, a, b) asm("fma.rn.f32x2 %0, %1, %2, %0;" : "+l"(acc) : "l"(a), "l"(b))

// -------- zero degree counters + detect edge dtype + convert W1 --------
#define CVT_W_CHUNKS (F_IN*HH/4)   // 8192
__global__ void k_zero(const int* __restrict__ ei32, const float* __restrict__ w) {
    int i = blockIdx.x * blockDim.x + threadIdx.x;
    if (i < N_NODES) { g_deg[i] = 1; g_cur[i] = 0; }   // deg=1 seeds self loop
    if (i < CVT_W_CHUNKS) {
        float4 v = ((const float4*)w)[i];
        __half2 a = __floats2half2_rn(v.x, v.y);
        __half2 b = __floats2half2_rn(v.z, v.w);
        uint2 st; st.x = *(unsigned*)&a; st.y = *(unsigned*)&b;
        ((uint2*)g_w1h)[i] = st;
    }
    if (blockIdx.x == 0) {
        __shared__ int nz;
        if (threadIdx.x == 0) nz = 0;
        __syncthreads();
        int c = 0;
        for (int k = threadIdx.x; k < 1024; k += blockDim.x)
            if (ei32[2*k + 1] != 0) c++;
        atomicAdd(&nz, c);
        __syncthreads();
        if (threadIdx.x == 0) g_fmt64 = (nz == 0) ? 1 : 0;
    }
}

// -------- count in-degrees (4 edges/thread, vectorized loads) --------
__global__ void k_count(const void* __restrict__ ei) {
    int t = blockIdx.x * blockDim.x + threadIdx.x;
    if (t >= EQ4) return;
    int d0, d1, d2, d3;
    if (g_fmt64) {
        const longlong2* ed = (const longlong2*)((const long long*)ei + N_EDGES);
        longlong2 a = ed[t*2], b = ed[t*2+1];
        d0 = (int)a.x; d1 = (int)a.y; d2 = (int)b.x; d3 = (int)b.y;
    } else {
        int4 v = ((const int4*)((const int*)ei + N_EDGES))[t];
        d0 = v.x; d1 = v.y; d2 = v.z; d3 = v.w;
    }
    atomicAdd(&g_deg[d0], 1);
    atomicAdd(&g_deg[d1], 1);
    atomicAdd(&g_deg[d2], 1);
    atomicAdd(&g_deg[d3], 1);
}

// -------- scan stage 1 --------
__global__ void k_scan1() {
    __shared__ int s[SCAN_BLK];
    int t = threadIdx.x;
    int i = blockIdx.x * SCAN_BLK + t;
    int v = (i < N_NODES) ? g_deg[i] : 0;
    s[t] = v;
    __syncthreads();
    for (int off = 1; off < SCAN_BLK; off <<= 1) {
        int x = (t >= off) ? s[t - off] : 0;
        __syncthreads();
        s[t] += x;
        __syncthreads();
    }
    if (i < N_NODES) g_scan[i] = s[t] - v;
    if (t == SCAN_BLK - 1) g_bsum[blockIdx.x] = s[t];
}

// -------- scan stages 2+3 merged --------
__global__ void k_scan23() {
    __shared__ int sb[NB];
    int t = threadIdx.x;
    if (t < NB) sb[t] = g_bsum[t];
    __syncthreads();
    if (t == 0) {
        int run = 0;
        for (int k = 0; k < NB; k++) { int v = sb[k]; sb[k] = run; run += v; }
    }
    __syncthreads();
    int i = blockIdx.x * blockDim.x + t;
    if (i < N_NODES) g_off[i] = g_scan[i] + sb[i / SCAN_BLK];
}

// -------- fill CSR (4 edges/thread + self-loop range) --------
__global__ void k_fill(const void* __restrict__ ei) {
    int t = blockIdx.x * blockDim.x + threadIdx.x;
    if (t < EQ4) {
        int s0,s1,s2,s3,d0,d1,d2,d3;
        if (g_fmt64) {
            const longlong2* es = (const longlong2*)ei;
            const longlong2* ed = (const longlong2*)((const long long*)ei + N_EDGES);
            longlong2 sa = es[t*2], sb = es[t*2+1];
            longlong2 da = ed[t*2], db = ed[t*2+1];
            s0=(int)sa.x; s1=(int)sa.y; s2=(int)sb.x; s3=(int)sb.y;
            d0=(int)da.x; d1=(int)da.y; d2=(int)db.x; d3=(int)db.y;
        } else {
            int4 sv = ((const int4*)ei)[t];
            int4 dv = ((const int4*)((const int*)ei + N_EDGES))[t];
            s0=sv.x; s1=sv.y; s2=sv.z; s3=sv.w;
            d0=dv.x; d1=dv.y; d2=dv.z; d3=dv.w;
        }
        int p0 = atomicAdd(&g_cur[d0], 1); g_adj[g_off[d0] + p0] = s0;
        int p1 = atomicAdd(&g_cur[d1], 1); g_adj[g_off[d1] + p1] = s1;
        int p2 = atomicAdd(&g_cur[d2], 1); g_adj[g_off[d2] + p2] = s2;
        int p3 = atomicAdd(&g_cur[d3], 1); g_adj[g_off[d3] + p3] = s3;
    } else {
        int n = t - EQ4;
        if (n < N_NODES) {
            int p = atomicAdd(&g_cur[n], 1);
            g_adj[g_off[n] + p] = n;
        }
    }
}

// -------- tensor-core GEMM: single K-stage (K=128 resident in SMEM) ----
#define PADH 136
#define MMA_SMEM (2*128*PADH*2)
__global__ void __launch_bounds__(256, 2)
k_mma(const float* __restrict__ X,
      const float* __restrict__ attS, const float* __restrict__ attD) {
    extern __shared__ __half dynsmem[];
    __half (*As)[PADH] = (__half(*)[PADH])dynsmem;
    __half (*Bs)[PADH] = (__half(*)[PADH])(dynsmem + 128*PADH);
    const int t    = threadIdx.x;
    const int lane = t & 31;
    const int wid  = t >> 5;
    const int wm   = wid & 3;
    const int wn   = wid >> 2;
    const int bm   = blockIdx.x * 128;
    const int bn   = blockIdx.y * 128;

#pragma unroll
    for (int it = 0; it < 8; it++) {
        int c  = t + it*256;
        int r  = c >> 4, cc = c & 15;
        int gr = bm + r;
        uint4 st = make_uint4(0u, 0u, 0u, 0u);
        if (gr < N_NODES) {
            const float4* xp = (const float4*)(X + (size_t)gr*F_IN + cc*8);
            float4 f0 = xp[0];
            float4 f1 = xp[1];
            __half2 h0 = __floats2half2_rn(f0.x, f0.y);
            __half2 h1 = __floats2half2_rn(f0.z, f0.w);
            __half2 h2 = __floats2half2_rn(f1.x, f1.y);
            __half2 h3 = __floats2half2_rn(f1.z, f1.w);
            st.x = *(unsigned*)&h0; st.y = *(unsigned*)&h1;
            st.z = *(unsigned*)&h2; st.w = *(unsigned*)&h3;
        }
        *(uint4*)&As[r][cc*8] = st;
    }
#pragma unroll
    for (int it = 0; it < 8; it++) {
        int c  = t + it*256;
        int kr = c >> 4, cc = c & 15;
        uint4 v = *(const uint4*)(g_w1h + (size_t)kr*HH + bn + cc*8);
        *(uint4*)&Bs[kr][cc*8] = v;
    }
    __syncthreads();

    float acc[2][8][4];
#pragma unroll
    for (int i = 0; i < 2; i++)
#pragma unroll
        for (int j = 0; j < 8; j++)
#pragma unroll
            for (int k = 0; k < 4; k++) acc[i][j][k] = 0.f;

    const int quad = lane >> 3;
#pragma unroll
    for (int ks = 0; ks < 8; ks++) {
        unsigned a[2][4];
#pragma unroll
        for (int mi = 0; mi < 2; mi++) {
            int row = wm*32 + mi*16 + (lane & 7) + (quad & 1)*8;
            int col = ks*16 + (quad >> 1)*8;
            ldmat4(a[mi][0], a[mi][1], a[mi][2], a[mi][3], s2u(&As[row][col]));
        }
        unsigned b[4][4];
#pragma unroll
        for (int ni = 0; ni < 4; ni++) {
            int krow = ks*16 + (lane & 7) + (quad & 1)*8;
            int col  = wn*64 + ni*16 + (quad >> 1)*8;
            ldmat4t(b[ni][0], b[ni][1], b[ni][2], b[ni][3], s2u(&Bs[krow][col]));
        }
#pragma unroll
        for (int mi = 0; mi < 2; mi++)
#pragma unroll
            for (int ni = 0; ni < 4; ni++) {
                mma16816(acc[mi][ni*2],   a[mi], b[ni][0], b[ni][1]);
                mma16816(acc[mi][ni*2+1], a[mi], b[ni][2], b[ni][3]);
            }
    }

    const int head = (bn >> 6) + wn;
#pragma unroll
    for (int mi = 0; mi < 2; mi++) {
        int r0 = bm + wm*32 + mi*16 + (lane >> 2);
        float pS0 = 0.f, pD0 = 0.f, pS8 = 0.f, pD8 = 0.f;
#pragma unroll
        for (int nj = 0; nj < 8; nj++) {
            int col = bn + wn*64 + nj*8 + (lane & 3)*2;
            float c0 = acc[mi][nj][0], c1 = acc[mi][nj][1];
            float c2 = acc[mi][nj][2], c3 = acc[mi][nj][3];
            float sS0 = attS[col], sS1 = attS[col+1];
            float sD0 = attD[col], sD1 = attD[col+1];
            pS0 += c0*sS0 + c1*sS1;  pD0 += c0*sD0 + c1*sD1;
            pS8 += c2*sS0 + c3*sS1;  pD8 += c2*sD0 + c3*sD1;
            if (r0 < N_NODES)
                g_h1h[(size_t)r0*128 + (col >> 1)] = __floats2half2_rn(c0, c1);
            if (r0 + 8 < N_NODES)
                g_h1h[(size_t)(r0+8)*128 + (col >> 1)] = __floats2half2_rn(c2, c3);
        }
#pragma unroll
        for (int o = 1; o <= 2; o <<= 1) {
            pS0 += __shfl_xor_sync(0xffffffffu, pS0, o);
            pD0 += __shfl_xor_sync(0xffffffffu, pD0, o);
            pS8 += __shfl_xor_sync(0xffffffffu, pS8, o);
            pD8 += __shfl_xor_sync(0xffffffffu, pD8, o);
        }
        if ((lane & 3) == 0) {
            if (r0 < N_NODES)     { g_as1[r0*4 + head]     = pS0; g_ad1[r0*4 + head]     = pD0; }
            if (r0 + 8 < N_NODES) { g_as1[(r0+8)*4 + head] = pS8; g_ad1[(r0+8)*4 + head] = pD8; }
        }
    }
}

// accumulate 8 fp16 channels, weighted, via packed f32x2 FMA
__device__ __forceinline__ void agg8p(float4 hv, unsigned long long eh2, unsigned long long* acc) {
    const __half2* ph = (const __half2*)&hv;
    float2 q0 = __half22float2(ph[0]);
    float2 q1 = __half22float2(ph[1]);
    float2 q2 = __half22float2(ph[2]);
    float2 q3 = __half22float2(ph[3]);
    unsigned long long p0, p1, p2, p3;
    PACK2(p0, q0.x, q0.y);
    PACK2(p1, q1.x, q1.y);
    PACK2(p2, q2.x, q2.y);
    PACK2(p3, q3.x, q3.y);
    FMA2(acc[0], p0, eh2);
    FMA2(acc[1], p1, eh2);
    FMA2(acc[2], p2, eh2);
    FMA2(acc[3], p3, eh2);
}

// -------- fused layer1: warp per dst, smem staging, MLP 8, packed FMA ----
__global__ void k_fused1(const float* __restrict__ b1, const float* __restrict__ W2,
                         const float* __restrict__ attS2, const float* __restrict__ attD2) {
    __shared__ __align__(16) int   sid[8][32];
    __shared__ __align__(16) float sex[8][4][32];
    int w     = (blockIdx.x * blockDim.x + threadIdx.x) >> 5;
    int lane  = threadIdx.x & 31;
    int wwarp = threadIdx.x >> 5;
    if (w >= N_NODES) return;
    const int beg = g_off[w];
    const int end = beg + g_deg[w];
    float4 ad = *(const float4*)(g_ad1 + w*4);

    const int hd = lane >> 3;            // head of this lane's channels [lane*8 .. +7]
    unsigned long long acc64[4] = {0ull, 0ull, 0ull, 0ull};
    float4 zs = make_float4(0.f, 0.f, 0.f, 0.f);
    const float4* hp = (const float4*)g_h1h;

    for (int base = beg; base < end; base += 32) {
        int j = base + lane;
        int s = 0;
        float4 ex = make_float4(0.f, 0.f, 0.f, 0.f);
        if (j < end) {
            s = g_adj[j];
            float4 as = *(const float4*)(g_as1 + s*4);
            ex.x = __expf(lrelu(as.x + ad.x));
            ex.y = __expf(lrelu(as.y + ad.y));
            ex.z = __expf(lrelu(as.z + ad.z));
            ex.w = __expf(lrelu(as.w + ad.w));
            zs.x += ex.x; zs.y += ex.y; zs.z += ex.z; zs.w += ex.w;
        }
        sid[wwarp][lane]    = s;
        sex[wwarp][0][lane] = ex.x;
        sex[wwarp][1][lane] = ex.y;
        sex[wwarp][2][lane] = ex.z;
        sex[wwarp][3][lane] = ex.w;
        __syncwarp();
        int cnt = min(32, end - base);
        int jj = 0;
        for (; jj + 8 <= cnt; jj += 8) {
            int4 ia = *(const int4*)&sid[wwarp][jj];
            int4 ib = *(const int4*)&sid[wwarp][jj+4];
            float4 wa = *(const float4*)&sex[wwarp][hd][jj];
            float4 wb = *(const float4*)&sex[wwarp][hd][jj+4];
            float4 v0 = hp[(size_t)ia.x*32 + lane];
            float4 v1 = hp[(size_t)ia.y*32 + lane];
            float4 v2 = hp[(size_t)ia.z*32 + lane];
            float4 v3 = hp[(size_t)ia.w*32 + lane];
            float4 v4 = hp[(size_t)ib.x*32 + lane];
            float4 v5 = hp[(size_t)ib.y*32 + lane];
            float4 v6 = hp[(size_t)ib.z*32 + lane];
            float4 v7 = hp[(size_t)ib.w*32 + lane];
            unsigned long long e2;
            PACK2(e2, wa.x, wa.x); agg8p(v0, e2, acc64);
            PACK2(e2, wa.y, wa.y); agg8p(v1, e2, acc64);
            PACK2(e2, wa.z, wa.z); agg8p(v2, e2, acc64);
            PACK2(e2, wa.w, wa.w); agg8p(v3, e2, acc64);
            PACK2(e2, wb.x, wb.x); agg8p(v4, e2, acc64);
            PACK2(e2, wb.y, wb.y); agg8p(v5, e2, acc64);
            PACK2(e2, wb.z, wb.z); agg8p(v6, e2, acc64);
            PACK2(e2, wb.w, wb.w); agg8p(v7, e2, acc64);
        }
        for (; jj < cnt; jj++) {
            int   ss = sid[wwarp][jj];
            float eh = sex[wwarp][hd][jj];
            float4 v = hp[(size_t)ss*32 + lane];
            unsigned long long e2;
            PACK2(e2, eh, eh);
            agg8p(v, e2, acc64);
        }
        __syncwarp();
    }
#pragma unroll
    for (int o = 16; o >= 1; o >>= 1) {
        zs.x += __shfl_xor_sync(0xffffffffu, zs.x, o);
        zs.y += __shfl_xor_sync(0xffffffffu, zs.y, o);
        zs.z += __shfl_xor_sync(0xffffffffu, zs.z, o);
        zs.w += __shfl_xor_sync(0xffffffffu, zs.w, o);
    }
    float acc[8];
    UNPACK2(acc[0], acc[1], acc64[0]);
    UNPACK2(acc[2], acc[3], acc64[1]);
    UNPACK2(acc[4], acc[5], acc64[2]);
    UNPACK2(acc[6], acc[7], acc64[3]);
    float zh = (hd == 0) ? zs.x : (hd == 1) ? zs.y : (hd == 2) ? zs.z : zs.w;
    float4 bA = *(const float4*)(b1 + lane*8);
    float4 bB = *(const float4*)(b1 + lane*8 + 4);
    float o0 = acc[0]/zh + bA.x, o1 = acc[1]/zh + bA.y;
    float o2 = acc[2]/zh + bA.z, o3 = acc[3]/zh + bA.w;
    float o4 = acc[4]/zh + bB.x, o5 = acc[5]/zh + bB.y;
    float o6 = acc[6]/zh + bB.z, o7 = acc[7]/zh + bB.w;
    o0 = o0 > 0.f ? o0 : (__expf(o0) - 1.f);
    o1 = o1 > 0.f ? o1 : (__expf(o1) - 1.f);
    o2 = o2 > 0.f ? o2 : (__expf(o2) - 1.f);
    o3 = o3 > 0.f ? o3 : (__expf(o3) - 1.f);
    o4 = o4 > 0.f ? o4 : (__expf(o4) - 1.f);
    o5 = o5 > 0.f ? o5 : (__expf(o5) - 1.f);
    o6 = o6 > 0.f ? o6 : (__expf(o6) - 1.f);
    o7 = o7 > 0.f ? o7 : (__expf(o7) - 1.f);
    const float4* Wv = (const float4*)(W2 + lane*16);
    float4 w0 = Wv[0], w1 = Wv[1], w2 = Wv[2], w3 = Wv[3];
    float s0 = o0*w0.x + o1*w0.z + o2*w1.x + o3*w1.z
             + o4*w2.x + o5*w2.z + o6*w3.x + o7*w3.z;
    float s1 = o0*w0.y + o1*w0.w + o2*w1.y + o3*w1.w
             + o4*w2.y + o5*w2.w + o6*w3.y + o7*w3.w;
#pragma unroll
    for (int o = 16; o >= 1; o >>= 1) {
        s0 += __shfl_xor_sync(0xffffffffu, s0, o);
        s1 += __shfl_xor_sync(0xffffffffu, s1, o);
    }
    if (lane == 0) {
        float as2 = s0*attS2[0] + s1*attS2[1];
        g_n2[w] = make_float4(s0, s1, as2, 0.f);
        g_ad2[w] = s0*attD2[0] + s1*attD2[1];
    }
}

// -------- fused layer2 (thread per dst, 4-deep MLP, one LDG.128/edge) ------
__global__ void k_fused2(float* __restrict__ out, const float* __restrict__ b2) {
    int t = blockIdx.x * blockDim.x + threadIdx.x;
    if (t >= N_NODES) return;
    const int beg = g_off[t];
    const int end = beg + g_deg[t];
    const float ad = g_ad2[t];
    float z = 0.f, a0 = 0.f, a1 = 0.f;
    int j = beg;
    for (; j + 4 <= end; j += 4) {
        int s0 = g_adj[j], s1 = g_adj[j+1], s2 = g_adj[j+2], s3 = g_adj[j+3];
        float4 n0 = g_n2[s0];
        float4 n1 = g_n2[s1];
        float4 n2 = g_n2[s2];
        float4 n3 = g_n2[s3];
        float e0 = __expf(lrelu(n0.z + ad));
        float e1 = __expf(lrelu(n1.z + ad));
        float e2 = __expf(lrelu(n2.z + ad));
        float e3 = __expf(lrelu(n3.z + ad));
        z  += e0 + e1 + e2 + e3;
        a0 += e0*n0.x + e1*n1.x + e2*n2.x + e3*n3.x;
        a1 += e0*n0.y + e1*n1.y + e2*n2.y + e3*n3.y;
    }
    for (; j < end; j++) {
        int s = g_adj[j];
        float4 n = g_n2[s];
        float ex = __expf(lrelu(n.z + ad));
        z  += ex;
        a0 += ex * n.x;
        a1 += ex * n.y;
    }
    out[2*t]   = a0 / z + b2[0];
    out[2*t+1] = a1 / z + b2[1];
}

extern "C" void kernel_launch(void* const* d_in, const int* in_sizes, int n_in,
                              void* d_out, int out_size) {
    const float* x    = (const float*)d_in[0];
    const void*  ei   = d_in[1];
    const float* W1   = (const float*)d_in[2];
    const float* aS1  = (const float*)d_in[3];
    const float* aD1  = (const float*)d_in[4];
    const float* b1   = (const float*)d_in[5];
    const float* W2   = (const float*)d_in[6];
    const float* aS2  = (const float*)d_in[7];
    const float* aD2  = (const float*)d_in[8];
    const float* b2   = (const float*)d_in[9];
    float* out = (float*)d_out;

    cudaFuncSetAttribute(k_mma, cudaFuncAttributeMaxDynamicSharedMemorySize, MMA_SMEM);

    cudaStream_t s1 = 0;
    cudaEvent_t evA = 0, evB = 0;
    bool par = (cudaStreamCreateWithFlags(&s1, cudaStreamNonBlocking) == cudaSuccess);
    if (par) par = (cudaEventCreateWithFlags(&evA, cudaEventDisableTiming) == cudaSuccess);
    if (par) par = (cudaEventCreateWithFlags(&evB, cudaEventDisableTiming) == cudaSuccess);
    cudaStream_t sb = par ? s1 : 0;

    const int TB = 256;
    k_zero<<<(N_NODES + TB - 1) / TB, TB>>>((const int*)ei, W1);
    if (par) {
        cudaEventRecord(evA, 0);
        cudaStreamWaitEvent(s1, evA, 0);
    }
    dim3 gg((N_NODES + 127) / 128, HH / 128);
    k_mma<<<gg, 256, MMA_SMEM>>>(x, aS1, aD1);
    k_count<<<(EQ4 + TB - 1) / TB, TB, 0, sb>>>(ei);
    k_scan1<<<NB, SCAN_BLK, 0, sb>>>();
    k_scan23<<<(N_NODES + TB - 1) / TB, TB, 0, sb>>>();
    k_fill<<<(EQ4 + N_NODES + TB - 1) / TB, TB, 0, sb>>>(ei);
    if (par) {
        cudaEventRecord(evB, s1);
        cudaStreamWaitEvent(0, evB, 0);
    }
    k_fused1<<<(N_NODES*32 + TB - 1) / TB, TB>>>(b1, W2, aS2, aD2);
    k_fused2<<<(N_NODES + TB - 1) / TB, TB>>>(out, b2);
}